// round 1
// baseline (speedup 1.0000x reference)
#include <cuda_runtime.h>

#define DIM        300
#define BATCH      256
#define W_ART      2048
#define W_OPT      64
#define CHUNKS     16
#define ROWS_PER_CHUNK (W_ART / CHUNKS)   // 128
#define OUT_STRIDE (2 * DIM)              // 600

// Grid: (BATCH, CHUNKS + 1). y < CHUNKS -> article chunk (atomicAdd partial mean);
// y == CHUNKS -> options (full reduction, direct store).
// Block: 320 threads, threads [0,300) each own one feature dim d.
__global__ void __launch_bounds__(320)
mean_concat_kernel(const float* __restrict__ art,
                   const float* __restrict__ opt,
                   float* __restrict__ out)
{
    const int b = blockIdx.x;
    const int c = blockIdx.y;
    const int d = threadIdx.x;
    if (d >= DIM) return;

    if (c < CHUNKS) {
        // article: sum ROWS_PER_CHUNK rows of this batch, dim d
        const float* p = art + ((size_t)b * W_ART + (size_t)c * ROWS_PER_CHUNK) * DIM + d;
        float s = 0.0f;
        #pragma unroll 8
        for (int w = 0; w < ROWS_PER_CHUNK; ++w) {
            s += p[(size_t)w * DIM];
        }
        atomicAdd(out + (size_t)b * OUT_STRIDE + d, s * (1.0f / (float)W_ART));
    } else {
        // options: full reduction over 64 rows, direct write (no atomic)
        const float* p = opt + (size_t)b * W_OPT * DIM + d;
        float s = 0.0f;
        #pragma unroll 8
        for (int w = 0; w < W_OPT; ++w) {
            s += p[(size_t)w * DIM];
        }
        out[(size_t)b * OUT_STRIDE + DIM + d] = s * (1.0f / (float)W_OPT);
    }
}

extern "C" void kernel_launch(void* const* d_in, const int* in_sizes, int n_in,
                              void* d_out, int out_size)
{
    const float* art = (const float*)d_in[0];   // [256, 2048, 300] f32
    const float* opt = (const float*)d_in[1];   // [256, 64, 300]   f32
    float* out = (float*)d_out;                 // [256, 600]       f32

    // Zero the output (article half accumulates via atomicAdd; poisoned to 0xAA).
    cudaMemsetAsync(out, 0, (size_t)out_size * sizeof(float));

    dim3 grid(BATCH, CHUNKS + 1);
    mean_concat_kernel<<<grid, 320>>>(art, opt, out);
}

// round 2
// speedup vs baseline: 1.0775x; 1.0775x over previous
#include <cuda_runtime.h>

#define DIM        300
#define DIM4       75            // DIM / 4 float4 per row
#define BATCH      256
#define W_ART      2048
#define W_OPT      64
#define CHUNKS     16
#define ROWS_PER_CHUNK (W_ART / CHUNKS)   // 128
#define OUT_STRIDE (2 * DIM)              // 600

// Grid: (BATCH, CHUNKS + 1). y < CHUNKS -> article chunk (partial sum -> smem -> one
// global atomicAdd per dim); y == CHUNKS -> options (full reduction, direct store).
// Block: 300 threads = 4 row-subgroups x 75 float4-columns. Each thread accumulates a
// float4 (4 dims) over rows {sub, sub+4, sub+8, ...} with fully-coalesced 512B/warp loads.
__global__ void __launch_bounds__(320)
mean_concat_kernel(const float* __restrict__ art,
                   const float* __restrict__ opt,
                   float* __restrict__ out)
{
    const int b   = blockIdx.x;
    const int c   = blockIdx.y;
    const int tid = threadIdx.x;           // 0..299
    const int col = tid % DIM4;            // float4 column 0..74
    const int sub = tid / DIM4;            // row subgroup 0..3

    __shared__ float s[DIM];
    s[tid] = 0.0f;
    __syncthreads();

    float4 acc = make_float4(0.f, 0.f, 0.f, 0.f);

    if (c < CHUNKS) {
        // article: rows [c*128, c*128+128), this thread does rows sub, sub+4, ...
        const float4* p = (const float4*)(art + ((size_t)b * W_ART + (size_t)c * ROWS_PER_CHUNK + sub) * DIM) + col;
        #pragma unroll 8
        for (int r = 0; r < ROWS_PER_CHUNK / 4; ++r) {
            float4 v = p[(size_t)r * (4 * DIM4)];    // advance 4 rows = 300 float4
            acc.x += v.x; acc.y += v.y; acc.z += v.z; acc.w += v.w;
        }
    } else {
        // options: 64 rows, this thread does 16 of them
        const float4* p = (const float4*)(opt + ((size_t)b * W_OPT + sub) * DIM) + col;
        #pragma unroll 8
        for (int r = 0; r < W_OPT / 4; ++r) {
            float4 v = p[(size_t)r * (4 * DIM4)];
            acc.x += v.x; acc.y += v.y; acc.z += v.z; acc.w += v.w;
        }
    }

    // Collapse the 4 subgroups in shared memory (spread addresses; conflict deg <= 4).
    atomicAdd(&s[4 * col + 0], acc.x);
    atomicAdd(&s[4 * col + 1], acc.y);
    atomicAdd(&s[4 * col + 2], acc.z);
    atomicAdd(&s[4 * col + 3], acc.w);
    __syncthreads();

    if (c < CHUNKS) {
        atomicAdd(out + (size_t)b * OUT_STRIDE + tid, s[tid] * (1.0f / (float)W_ART));
    } else {
        out[(size_t)b * OUT_STRIDE + DIM + tid] = s[tid] * (1.0f / (float)W_OPT);
    }
}

extern "C" void kernel_launch(void* const* d_in, const int* in_sizes, int n_in,
                              void* d_out, int out_size)
{
    const float* art = (const float*)d_in[0];   // [256, 2048, 300] f32
    const float* opt = (const float*)d_in[1];   // [256, 64, 300]   f32
    float* out = (float*)d_out;                 // [256, 600]       f32

    // Zero the output (article half accumulates via atomicAdd; buffer poisoned to 0xAA).
    cudaMemsetAsync(out, 0, (size_t)out_size * sizeof(float));

    dim3 grid(BATCH, CHUNKS + 1);
    mean_concat_kernel<<<grid, 300>>>(art, opt, out);
}

// round 5
// speedup vs baseline: 1.0847x; 1.0066x over previous
#include <cuda_runtime.h>

#define DIM        300
#define DIM4       75            // DIM / 4 float4 per row
#define BATCH      256
#define W_ART      2048
#define W_OPT      64
#define CHUNKS     32
#define ROWS_PER_CHUNK (W_ART / CHUNKS)   // 64
#define OUT_STRIDE (2 * DIM)              // 600

// Grid: (BATCH, CHUNKS + 1). y < CHUNKS -> article chunk (partial sum -> smem -> one
// global atomicAdd per dim); y == CHUNKS -> options (full reduction, direct store).
// Block: 300 threads = 4 row-subgroups x 75 float4-columns. Each thread owns exactly
// 16 rows (fully unrolled -> 16 front-batched LDG.128 per thread for deep MLP).
__global__ void __launch_bounds__(320)
mean_concat_kernel(const float* __restrict__ art,
                   const float* __restrict__ opt,
                   float* __restrict__ out)
{
    const int b   = blockIdx.x;
    const int c   = blockIdx.y;
    const int tid = threadIdx.x;           // 0..299
    const int col = tid % DIM4;            // float4 column 0..74
    const int sub = tid / DIM4;            // row subgroup 0..3

    __shared__ float s[DIM];
    s[tid] = 0.0f;
    __syncthreads();

    float4 acc = make_float4(0.f, 0.f, 0.f, 0.f);

    if (c < CHUNKS) {
        // article: rows [c*64, c*64+64); this thread does rows sub, sub+4, ... (16 rows)
        const float4* p = (const float4*)(art + ((size_t)b * W_ART + (size_t)c * ROWS_PER_CHUNK + sub) * DIM) + col;
        #pragma unroll
        for (int r = 0; r < ROWS_PER_CHUNK / 4; ++r) {   // 16 iters, fully unrolled
            float4 v = p[(size_t)r * (4 * DIM4)];        // advance 4 rows = 300 float4
            acc.x += v.x; acc.y += v.y; acc.z += v.z; acc.w += v.w;
        }
    } else {
        // options: 64 rows; this thread does 16 of them (fully unrolled)
        const float4* p = (const float4*)(opt + ((size_t)b * W_OPT + sub) * DIM) + col;
        #pragma unroll
        for (int r = 0; r < W_OPT / 4; ++r) {            // 16 iters
            float4 v = p[(size_t)r * (4 * DIM4)];
            acc.x += v.x; acc.y += v.y; acc.z += v.z; acc.w += v.w;
        }
    }

    // Collapse the 4 subgroups in shared memory (spread addresses; conflict deg <= 4).
    atomicAdd(&s[4 * col + 0], acc.x);
    atomicAdd(&s[4 * col + 1], acc.y);
    atomicAdd(&s[4 * col + 2], acc.z);
    atomicAdd(&s[4 * col + 3], acc.w);
    __syncthreads();

    if (c < CHUNKS) {
        atomicAdd(out + (size_t)b * OUT_STRIDE + tid, s[tid] * (1.0f / (float)W_ART));
    } else {
        out[(size_t)b * OUT_STRIDE + DIM + tid] = s[tid] * (1.0f / (float)W_OPT);
    }
}

extern "C" void kernel_launch(void* const* d_in, const int* in_sizes, int n_in,
                              void* d_out, int out_size)
{
    const float* art = (const float*)d_in[0];   // [256, 2048, 300] f32
    const float* opt = (const float*)d_in[1];   // [256, 64, 300]   f32
    float* out = (float*)d_out;                 // [256, 600]       f32

    // Zero the output (article half accumulates via atomicAdd; buffer poisoned to 0xAA).
    cudaMemsetAsync(out, 0, (size_t)out_size * sizeof(float));

    dim3 grid(BATCH, CHUNKS + 1);
    mean_concat_kernel<<<grid, 300>>>(art, opt, out);
}